// round 1
// baseline (speedup 1.0000x reference)
#include <cuda_runtime.h>

#define N_NODES 4096
#define KNBR 32
#define CDIM 128
#define VDIM 21
#define SMEM_BYTES ((CDIM*CDIM + KNBR*CDIM) * 4)

__device__ float g_A[CDIM];        // nodevec @ Wl2_top
__device__ float g_const[CDIM];    // xr + br2 + bl2 + be2  (constant part of m)
__device__ float g_T[VDIM * CDIM]; // W_s @ Wl2_bot

__device__ __forceinline__ float lrelu(float x) { return x > 0.f ? x : 0.2f * x; }

// One block, 128 threads: precompute the tiny constant tensors.
__global__ void setup_kernel(const float* __restrict__ bl1, const float* __restrict__ bo1,
                             const float* __restrict__ Wl2, const float* __restrict__ bl2,
                             const float* __restrict__ Wr2, const float* __restrict__ br2,
                             const float* __restrict__ be2, const float* __restrict__ Ws) {
    int c = threadIdx.x;
    __shared__ float nv[CDIM];
    nv[c] = bl1[c] + bo1[c];
    __syncthreads();
    float a = 0.f, x = 0.f;
    #pragma unroll 8
    for (int j = 0; j < CDIM; j++) {
        a = fmaf(nv[j], Wl2[j * CDIM + c], a);
        x = fmaf(nv[j], Wr2[j * CDIM + c], x);
    }
    g_A[c] = a;
    g_const[c] = x + br2[c] + bl2[c] + be2[c];
    for (int v = 0; v < VDIM; v++) {
        float t = 0.f;
        #pragma unroll 8
        for (int h = 0; h < CDIM; h++)
            t = fmaf(Ws[v * CDIM + h], Wl2[(CDIM + h) * CDIM + c], t);
        g_T[v * CDIM + c] = t;
    }
}

__global__ void __launch_bounds__(128, 2)
main_kernel(const float* __restrict__ E, const int* __restrict__ E_idx,
            const int* __restrict__ S, const float* __restrict__ mask,
            const float* __restrict__ chain_M, const float* __restrict__ z,
            const float* __restrict__ We2, const float* __restrict__ a2,
            const float* __restrict__ bl2, const float* __restrict__ bo2,
            const float* __restrict__ W_out, const float* __restrict__ b_out,
            float* __restrict__ out) {
    extern __shared__ float smem[];
    float* sW = smem;                 // 128x128 We2
    float* sE = smem + CDIM * CDIM;   // 32x128 E tile
    __shared__ float sLogit[KNBR];
    __shared__ float sAW[KNBR];
    __shared__ float sWk[KNBR];
    __shared__ int   sSk[KNBR];
    __shared__ float sOut[CDIM];
    __shared__ float sLg[VDIM];
    __shared__ float sRed[2];

    const int tid = threadIdx.x;
    const int tx = tid & 31;
    const int ty = tid >> 5;

    // Load We2 once per (persistent) block.
    {
        float4* d = (float4*)sW;
        const float4* s = (const float4*)We2;
        #pragma unroll
        for (int i = 0; i < 32; i++) d[i * 128 + tid] = s[i * 128 + tid];
    }

    for (int n = blockIdx.x; n < N_NODES; n += gridDim.x) {
        __syncthreads();  // protect smem reuse across iterations

        // Load E tile for node n.
        {
            float4* d = (float4*)sE;
            const float4* s = (const float4*)(E + (size_t)n * KNBR * CDIM);
            #pragma unroll
            for (int i = 0; i < 8; i++) d[i * 128 + tid] = s[i * 128 + tid];
        }
        const float maskn = mask[n];
        if (tid < KNBR) {
            int e = E_idx[n * KNBR + tid];
            // stable argsort rank comparison == lexicographic (key, index) comparison
            float kn = __fmul_rn(__fadd_rn(__fmul_rn(chain_M[n], mask[n]), 1e-4f), fabsf(z[n]));
            float ke = __fmul_rn(__fadd_rn(__fmul_rn(chain_M[e], mask[e]), 1e-4f), fabsf(z[e]));
            float attend = (kn > ke || (kn == ke && n > e)) ? 1.f : 0.f;
            sWk[tid] = attend * maskn;
            sSk[tid] = S[e];
        }
        __syncthreads();

        // GEMM: M[k][c] = sum_j E[k][j] * We2[j][c]; thread owns k=ty*8..+7, c=4*tx..+3
        float acc[8][4];
        #pragma unroll
        for (int kk = 0; kk < 8; kk++)
            #pragma unroll
            for (int ci = 0; ci < 4; ci++) acc[kk][ci] = 0.f;

        const float4* sW4 = (const float4*)sW;
        const float4* sE4 = (const float4*)(sE + (ty * 8) * CDIM);
        #pragma unroll 4
        for (int j4 = 0; j4 < 32; j4++) {
            float wreg[16];
            #pragma unroll
            for (int js = 0; js < 4; js++) {
                float4 t = sW4[(4 * j4 + js) * 32 + tx];
                wreg[js * 4 + 0] = t.x; wreg[js * 4 + 1] = t.y;
                wreg[js * 4 + 2] = t.z; wreg[js * 4 + 3] = t.w;
            }
            #pragma unroll
            for (int kk = 0; kk < 8; kk++) {
                float4 e4 = sE4[kk * 32 + j4];
                float ereg[4] = {e4.x, e4.y, e4.z, e4.w};
                #pragma unroll
                for (int js = 0; js < 4; js++)
                    #pragma unroll
                    for (int ci = 0; ci < 4; ci++)
                        acc[kk][ci] = fmaf(ereg[js], wreg[js * 4 + ci], acc[kk][ci]);
            }
        }

        // attention logits: logit[k] = sum_c lrelu(M[k][c] + add[c] + T[s_k][c]*w_k) * a2[c]
        {
            float4 vA = ((const float4*)g_A)[tx];
            float4 vC = ((const float4*)g_const)[tx];
            float4 v2 = ((const float4*)a2)[tx];
            float add0 = vC.x + vA.x * maskn;
            float add1 = vC.y + vA.y * maskn;
            float add2 = vC.z + vA.z * maskn;
            float add3 = vC.w + vA.w * maskn;
            #pragma unroll
            for (int kk = 0; kk < 8; kk++) {
                int k = ty * 8 + kk;
                float wk = sWk[k];
                float4 tv = ((const float4*)(g_T + sSk[k] * CDIM))[tx];
                float m0 = acc[kk][0] + add0 + tv.x * wk;
                float m1 = acc[kk][1] + add1 + tv.y * wk;
                float m2 = acc[kk][2] + add2 + tv.z * wk;
                float m3 = acc[kk][3] + add3 + tv.w * wk;
                float p = lrelu(m0) * v2.x + lrelu(m1) * v2.y +
                          lrelu(m2) * v2.z + lrelu(m3) * v2.w;
                #pragma unroll
                for (int off = 16; off; off >>= 1)
                    p += __shfl_xor_sync(0xffffffffu, p, off);
                if (tx == 0) sLogit[k] = p;
            }
        }
        __syncthreads();

        // softmax over K=32 (warp 0), fold in w_k for the output sum
        if (ty == 0) {
            float l = sLogit[tx];
            float mx = l;
            #pragma unroll
            for (int off = 16; off; off >>= 1)
                mx = fmaxf(mx, __shfl_xor_sync(0xffffffffu, mx, off));
            float e = expf(l - mx);
            float s = e;
            #pragma unroll
            for (int off = 16; off; off >>= 1)
                s += __shfl_xor_sync(0xffffffffu, s, off);
            sAW[tx] = (e / s) * sWk[tx];
        }
        __syncthreads();

        // out[c] = A[c]*mask + bl2 + bo2 + sum_k (alpha_k*w_k) T[s_k][c]
        {
            float o = g_A[tid] * maskn + bl2[tid] + bo2[tid];
            #pragma unroll
            for (int k = 0; k < KNBR; k++)
                o = fmaf(sAW[k], g_T[sSk[k] * CDIM + tid], o);
            sOut[tid] = o;
        }
        __syncthreads();

        // logits (V=21) + log_softmax
        if (tid < VDIM) {
            float L = b_out[tid];
            #pragma unroll 8
            for (int c = 0; c < CDIM; c++)
                L = fmaf(sOut[c], W_out[c * VDIM + tid], L);
            sLg[tid] = L;
        }
        __syncthreads();
        if (tid == 0) {
            float mx = sLg[0];
            for (int v = 1; v < VDIM; v++) mx = fmaxf(mx, sLg[v]);
            float s = 0.f;
            for (int v = 0; v < VDIM; v++) s += expf(sLg[v] - mx);
            sRed[0] = mx;
            sRed[1] = logf(s);
        }
        __syncthreads();
        if (tid < VDIM)
            out[n * VDIM + tid] = sLg[tid] - sRed[0] - sRed[1];
    }
}

extern "C" void kernel_launch(void* const* d_in, const int* in_sizes, int n_in,
                              void* d_out, int out_size) {
    const float* E       = (const float*)d_in[0];
    const int*   E_idx   = (const int*)  d_in[1];
    const int*   S       = (const int*)  d_in[2];
    const float* mask    = (const float*)d_in[3];
    const float* chain_M = (const float*)d_in[4];
    const float* z       = (const float*)d_in[5];
    const float* bl1     = (const float*)d_in[7];
    const float* bo1     = (const float*)d_in[13];
    const float* Wl2     = (const float*)d_in[14];
    const float* bl2     = (const float*)d_in[15];
    const float* Wr2     = (const float*)d_in[16];
    const float* br2     = (const float*)d_in[17];
    const float* We2     = (const float*)d_in[18];
    const float* be2     = (const float*)d_in[19];
    const float* a2      = (const float*)d_in[20];
    const float* bo2     = (const float*)d_in[21];
    const float* Ws      = (const float*)d_in[22];
    const float* W_out   = (const float*)d_in[23];
    const float* b_out   = (const float*)d_in[24];
    float* out = (float*)d_out;

    cudaFuncSetAttribute(main_kernel, cudaFuncAttributeMaxDynamicSharedMemorySize, SMEM_BYTES);

    setup_kernel<<<1, 128>>>(bl1, bo1, Wl2, bl2, Wr2, br2, be2, Ws);
    main_kernel<<<304, 128, SMEM_BYTES>>>(E, E_idx, S, mask, chain_M, z,
                                          We2, a2, bl2, bo2, W_out, b_out, out);
}

// round 2
// speedup vs baseline: 1.0090x; 1.0090x over previous
#include <cuda_runtime.h>

#define N_NODES 4096
#define KNBR 32
#define CDIM 128
#define VDIM 21
#define SMEM_BYTES ((CDIM*CDIM + KNBR*CDIM) * 4)

__device__ float g_A[CDIM];        // nodevec @ Wl2_top
__device__ float g_const[CDIM];    // xr + br2 + bl2 + be2  (constant part of m)
__device__ float g_T[VDIM * CDIM]; // W_s @ Wl2_bot

__device__ __forceinline__ float lrelu(float x) { return x > 0.f ? x : 0.2f * x; }

// One block, 128 threads: precompute the tiny constant tensors.
__global__ void setup_kernel(const float* __restrict__ bl1, const float* __restrict__ bo1,
                             const float* __restrict__ Wl2, const float* __restrict__ bl2,
                             const float* __restrict__ Wr2, const float* __restrict__ br2,
                             const float* __restrict__ be2, const float* __restrict__ Ws) {
    int c = threadIdx.x;
    __shared__ float nv[CDIM];
    nv[c] = bl1[c] + bo1[c];
    __syncthreads();
    float a = 0.f, x = 0.f;
    #pragma unroll 8
    for (int j = 0; j < CDIM; j++) {
        a = fmaf(nv[j], Wl2[j * CDIM + c], a);
        x = fmaf(nv[j], Wr2[j * CDIM + c], x);
    }
    g_A[c] = a;
    g_const[c] = x + br2[c] + bl2[c] + be2[c];
    for (int v = 0; v < VDIM; v++) {
        float t = 0.f;
        #pragma unroll 8
        for (int h = 0; h < CDIM; h++)
            t = fmaf(Ws[v * CDIM + h], Wl2[(CDIM + h) * CDIM + c], t);
        g_T[v * CDIM + c] = t;
    }
}

__global__ void __launch_bounds__(128, 2)
main_kernel(const float* __restrict__ E, const int* __restrict__ E_idx,
            const int* __restrict__ S, const float* __restrict__ mask,
            const float* __restrict__ chain_M, const float* __restrict__ z,
            const float* __restrict__ We2, const float* __restrict__ a2,
            const float* __restrict__ bl2, const float* __restrict__ bo2,
            const float* __restrict__ W_out, const float* __restrict__ b_out,
            float* __restrict__ out) {
    extern __shared__ float smem[];
    float* sW = smem;                 // 128x128 We2
    float* sE = smem + CDIM * CDIM;   // 32x128 E tile
    __shared__ float sLogit[KNBR];
    __shared__ float sAW[KNBR];
    __shared__ float sWk[KNBR];
    __shared__ int   sSk[KNBR];
    __shared__ float sOut[CDIM];
    __shared__ float sLg[VDIM];
    __shared__ float sRed[2];

    const int tid = threadIdx.x;
    const int tx = tid & 31;
    const int ty = tid >> 5;

    // Load We2 once per (persistent) block.
    {
        float4* d = (float4*)sW;
        const float4* s = (const float4*)We2;
        #pragma unroll
        for (int i = 0; i < 32; i++) d[i * 128 + tid] = s[i * 128 + tid];
    }

    for (int n = blockIdx.x; n < N_NODES; n += gridDim.x) {
        __syncthreads();  // protect smem reuse across iterations

        // Load E tile for node n.
        {
            float4* d = (float4*)sE;
            const float4* s = (const float4*)(E + (size_t)n * KNBR * CDIM);
            #pragma unroll
            for (int i = 0; i < 8; i++) d[i * 128 + tid] = s[i * 128 + tid];
        }
        const float maskn = mask[n];
        if (tid < KNBR) {
            int e = E_idx[n * KNBR + tid];
            // stable argsort rank comparison == lexicographic (key, index) comparison
            float kn = __fmul_rn(__fadd_rn(__fmul_rn(chain_M[n], mask[n]), 1e-4f), fabsf(z[n]));
            float ke = __fmul_rn(__fadd_rn(__fmul_rn(chain_M[e], mask[e]), 1e-4f), fabsf(z[e]));
            float attend = (kn > ke || (kn == ke && n > e)) ? 1.f : 0.f;
            sWk[tid] = attend * maskn;
            sSk[tid] = S[e];
        }
        __syncthreads();

        // GEMM: M[k][c] = sum_j E[k][j] * We2[j][c]; thread owns k=ty*8..+7, c=4*tx..+3
        float acc[8][4];
        #pragma unroll
        for (int kk = 0; kk < 8; kk++)
            #pragma unroll
            for (int ci = 0; ci < 4; ci++) acc[kk][ci] = 0.f;

        const float4* sW4 = (const float4*)sW;
        const float4* sE4 = (const float4*)(sE + (ty * 8) * CDIM);
        #pragma unroll 4
        for (int j4 = 0; j4 < 32; j4++) {
            float wreg[16];
            #pragma unroll
            for (int js = 0; js < 4; js++) {
                float4 t = sW4[(4 * j4 + js) * 32 + tx];
                wreg[js * 4 + 0] = t.x; wreg[js * 4 + 1] = t.y;
                wreg[js * 4 + 2] = t.z; wreg[js * 4 + 3] = t.w;
            }
            #pragma unroll
            for (int kk = 0; kk < 8; kk++) {
                float4 e4 = sE4[kk * 32 + j4];
                float ereg[4] = {e4.x, e4.y, e4.z, e4.w};
                #pragma unroll
                for (int js = 0; js < 4; js++)
                    #pragma unroll
                    for (int ci = 0; ci < 4; ci++)
                        acc[kk][ci] = fmaf(ereg[js], wreg[js * 4 + ci], acc[kk][ci]);
            }
        }

        // attention logits: logit[k] = sum_c lrelu(M[k][c] + add[c] + T[s_k][c]*w_k) * a2[c]
        {
            float4 vA = ((const float4*)g_A)[tx];
            float4 vC = ((const float4*)g_const)[tx];
            float4 v2 = ((const float4*)a2)[tx];
            float add0 = vC.x + vA.x * maskn;
            float add1 = vC.y + vA.y * maskn;
            float add2 = vC.z + vA.z * maskn;
            float add3 = vC.w + vA.w * maskn;
            #pragma unroll
            for (int kk = 0; kk < 8; kk++) {
                int k = ty * 8 + kk;
                float wk = sWk[k];
                float4 tv = ((const float4*)(g_T + sSk[k] * CDIM))[tx];
                float m0 = acc[kk][0] + add0 + tv.x * wk;
                float m1 = acc[kk][1] + add1 + tv.y * wk;
                float m2 = acc[kk][2] + add2 + tv.z * wk;
                float m3 = acc[kk][3] + add3 + tv.w * wk;
                float p = lrelu(m0) * v2.x + lrelu(m1) * v2.y +
                          lrelu(m2) * v2.z + lrelu(m3) * v2.w;
                #pragma unroll
                for (int off = 16; off; off >>= 1)
                    p += __shfl_xor_sync(0xffffffffu, p, off);
                if (tx == 0) sLogit[k] = p;
            }
        }
        __syncthreads();

        // softmax over K=32 (warp 0), fold in w_k for the output sum
        if (ty == 0) {
            float l = sLogit[tx];
            float mx = l;
            #pragma unroll
            for (int off = 16; off; off >>= 1)
                mx = fmaxf(mx, __shfl_xor_sync(0xffffffffu, mx, off));
            float e = expf(l - mx);
            float s = e;
            #pragma unroll
            for (int off = 16; off; off >>= 1)
                s += __shfl_xor_sync(0xffffffffu, s, off);
            sAW[tx] = (e / s) * sWk[tx];
        }
        __syncthreads();

        // out[c] = A[c]*mask + bl2 + bo2 + sum_k (alpha_k*w_k) T[s_k][c]
        {
            float o = g_A[tid] * maskn + bl2[tid] + bo2[tid];
            #pragma unroll
            for (int k = 0; k < KNBR; k++)
                o = fmaf(sAW[k], g_T[sSk[k] * CDIM + tid], o);
            sOut[tid] = o;
        }
        __syncthreads();

        // logits (V=21) + log_softmax
        if (tid < VDIM) {
            float L = b_out[tid];
            #pragma unroll 8
            for (int c = 0; c < CDIM; c++)
                L = fmaf(sOut[c], W_out[c * VDIM + tid], L);
            sLg[tid] = L;
        }
        __syncthreads();
        if (tid == 0) {
            float mx = sLg[0];
            for (int v = 1; v < VDIM; v++) mx = fmaxf(mx, sLg[v]);
            float s = 0.f;
            for (int v = 0; v < VDIM; v++) s += expf(sLg[v] - mx);
            sRed[0] = mx;
            sRed[1] = logf(s);
        }
        __syncthreads();
        if (tid < VDIM)
            out[n * VDIM + tid] = sLg[tid] - sRed[0] - sRed[1];
    }
}

extern "C" void kernel_launch(void* const* d_in, const int* in_sizes, int n_in,
                              void* d_out, int out_size) {
    const float* E       = (const float*)d_in[0];
    const int*   E_idx   = (const int*)  d_in[1];
    const int*   S       = (const int*)  d_in[2];
    const float* mask    = (const float*)d_in[3];
    const float* chain_M = (const float*)d_in[4];
    const float* z       = (const float*)d_in[5];
    const float* bl1     = (const float*)d_in[7];
    const float* bo1     = (const float*)d_in[13];
    const float* Wl2     = (const float*)d_in[14];
    const float* bl2     = (const float*)d_in[15];
    const float* Wr2     = (const float*)d_in[16];
    const float* br2     = (const float*)d_in[17];
    const float* We2     = (const float*)d_in[18];
    const float* be2     = (const float*)d_in[19];
    const float* a2      = (const float*)d_in[20];
    const float* bo2     = (const float*)d_in[21];
    const float* Ws      = (const float*)d_in[22];
    const float* W_out   = (const float*)d_in[23];
    const float* b_out   = (const float*)d_in[24];
    float* out = (float*)d_out;

    cudaFuncSetAttribute(main_kernel, cudaFuncAttributeMaxDynamicSharedMemorySize, SMEM_BYTES);

    setup_kernel<<<1, 128>>>(bl1, bo1, Wl2, bl2, Wr2, br2, be2, Ws);
    main_kernel<<<304, 128, SMEM_BYTES>>>(E, E_idx, S, mask, chain_M, z,
                                          We2, a2, bl2, bo2, W_out, b_out, out);
}

// round 5
// speedup vs baseline: 1.6145x; 1.6000x over previous
#include <cuda_runtime.h>

#define N_NODES 4096
#define KNBR 32
#define CDIM 128
#define VDIM 21
// We2 (64KB) + two E tiles (2 x 16KB) = 96KB dynamic smem per block
#define SMEM_BYTES ((CDIM*CDIM + 2*KNBR*CDIM) * 4)

__device__ float g_A[CDIM];        // nodevec @ Wl2_top
__device__ float g_const[CDIM];    // xr + br2 + bl2 + be2  (constant part of m)
__device__ float g_T[VDIM * CDIM]; // W_s @ Wl2_bot

__device__ __forceinline__ float lrelu(float x) { return x > 0.f ? x : 0.2f * x; }

__device__ __forceinline__ unsigned long long pack2(float lo, float hi) {
    unsigned long long r;
    asm("mov.b64 %0, {%1, %2};" : "=l"(r) : "f"(lo), "f"(hi));
    return r;
}
__device__ __forceinline__ void ffma2(unsigned long long& d,
                                      unsigned long long a, unsigned long long b) {
    asm("fma.rn.f32x2 %0, %1, %2, %0;" : "+l"(d) : "l"(a), "l"(b));
}
__device__ __forceinline__ float2 unpack2(unsigned long long v) {
    float2 r;
    asm("mov.b64 {%0, %1}, %2;" : "=f"(r.x), "=f"(r.y) : "l"(v));
    return r;
}

// 22 blocks x 128 threads: block 0 -> g_A/g_const, blocks 1..21 -> g_T rows.
__global__ void setup_kernel(const float* __restrict__ bl1, const float* __restrict__ bo1,
                             const float* __restrict__ Wl2, const float* __restrict__ bl2,
                             const float* __restrict__ Wr2, const float* __restrict__ br2,
                             const float* __restrict__ be2, const float* __restrict__ Ws) {
    int c = threadIdx.x;
    int b = blockIdx.x;
    if (b == 0) {
        __shared__ float nv[CDIM];
        nv[c] = bl1[c] + bo1[c];
        __syncthreads();
        float a = 0.f, x = 0.f;
        #pragma unroll 8
        for (int j = 0; j < CDIM; j++) {
            a = fmaf(nv[j], Wl2[j * CDIM + c], a);
            x = fmaf(nv[j], Wr2[j * CDIM + c], x);
        }
        g_A[c] = a;
        g_const[c] = x + br2[c] + bl2[c] + be2[c];
    } else {
        int v = b - 1;
        float t = 0.f;
        #pragma unroll 8
        for (int h = 0; h < CDIM; h++)
            t = fmaf(Ws[v * CDIM + h], Wl2[(CDIM + h) * CDIM + c], t);
        g_T[v * CDIM + c] = t;
    }
}

__global__ void __launch_bounds__(256, 2)
main_kernel(const float* __restrict__ E, const int* __restrict__ E_idx,
            const int* __restrict__ S, const float* __restrict__ mask,
            const float* __restrict__ chain_M, const float* __restrict__ z,
            const float* __restrict__ We2, const float* __restrict__ a2,
            const float* __restrict__ bl2, const float* __restrict__ bo2,
            const float* __restrict__ W_out, const float* __restrict__ b_out,
            float* __restrict__ out) {
    extern __shared__ float smem[];
    float* sW = smem;                 // 128x128 We2
    float* sE = smem + CDIM * CDIM;   // [2][32x128] E tiles
    __shared__ float sLogit[2][KNBR];
    __shared__ float sAW[2][KNBR];
    __shared__ float sWk[2][KNBR];
    __shared__ int   sSk[2][KNBR];
    __shared__ float sOut[2][CDIM];
    __shared__ float sLg[2][VDIM];
    __shared__ float sRed[2][2];

    const int tid = threadIdx.x;
    const int g  = tid >> 7;          // node group 0/1 within the block
    const int t  = tid & 127;         // thread id within group
    const int tx = tid & 31;
    const int ty = t >> 5;            // warp-in-group 0..3

    // Load We2 once per (persistent) block, all 256 threads.
    {
        float4* d = (float4*)sW;
        const float4* s = (const float4*)We2;
        #pragma unroll
        for (int i = 0; i < 16; i++) d[i * 256 + tid] = s[i * 256 + tid];
    }

    float* sEg = sE + g * (KNBR * CDIM);

    for (int p = blockIdx.x; p < N_NODES / 2; p += gridDim.x) {
        const int n = p * 2 + g;
        __syncthreads();  // protect smem reuse across iterations

        // Load this group's E tile (16KB, 128 threads).
        {
            float4* d = (float4*)sEg;
            const float4* s = (const float4*)(E + (size_t)n * KNBR * CDIM);
            #pragma unroll
            for (int i = 0; i < 8; i++) d[i * 128 + t] = s[i * 128 + t];
        }
        const float maskn = mask[n];
        if (t < KNBR) {
            int e = E_idx[n * KNBR + t];
            // stable argsort rank comparison == lexicographic (key, index) comparison
            float kn = __fmul_rn(__fadd_rn(__fmul_rn(chain_M[n], mask[n]), 1e-4f), fabsf(z[n]));
            float ke = __fmul_rn(__fadd_rn(__fmul_rn(chain_M[e], mask[e]), 1e-4f), fabsf(z[e]));
            float attend = (kn > ke || (kn == ke && n > e)) ? 1.f : 0.f;
            sWk[g][t] = attend * maskn;
            sSk[g][t] = S[e];
        }
        __syncthreads();

        // GEMM: M[k][c] = sum_j E[k][j] * We2[j][c]
        // thread owns k = ty*8..+7, c = 4*tx..+3, accumulated as f32x2 pairs.
        unsigned long long acc[8][2];
        #pragma unroll
        for (int kk = 0; kk < 8; kk++) { acc[kk][0] = 0ull; acc[kk][1] = 0ull; }

        const float4* sW4 = (const float4*)sW;
        const float4* sE4 = (const float4*)(sEg + (ty * 8) * CDIM);
        #pragma unroll 2
        for (int j4 = 0; j4 < 32; j4++) {
            unsigned long long wp[4][2];
            #pragma unroll
            for (int js = 0; js < 4; js++) {
                float4 tw = sW4[(4 * j4 + js) * 32 + tx];
                wp[js][0] = pack2(tw.x, tw.y);
                wp[js][1] = pack2(tw.z, tw.w);
            }
            #pragma unroll
            for (int kk = 0; kk < 8; kk++) {
                float4 e4 = sE4[kk * 32 + j4];
                unsigned long long ep;
                ep = pack2(e4.x, e4.x);
                ffma2(acc[kk][0], ep, wp[0][0]); ffma2(acc[kk][1], ep, wp[0][1]);
                ep = pack2(e4.y, e4.y);
                ffma2(acc[kk][0], ep, wp[1][0]); ffma2(acc[kk][1], ep, wp[1][1]);
                ep = pack2(e4.z, e4.z);
                ffma2(acc[kk][0], ep, wp[2][0]); ffma2(acc[kk][1], ep, wp[2][1]);
                ep = pack2(e4.w, e4.w);
                ffma2(acc[kk][0], ep, wp[3][0]); ffma2(acc[kk][1], ep, wp[3][1]);
            }
        }

        // attention logits: logit[k] = sum_c lrelu(M[k][c] + add[c] + T[s_k][c]*w_k) * a2[c]
        {
            float4 vA = ((const float4*)g_A)[tx];
            float4 vC = ((const float4*)g_const)[tx];
            float4 v2 = ((const float4*)a2)[tx];
            float add0 = vC.x + vA.x * maskn;
            float add1 = vC.y + vA.y * maskn;
            float add2 = vC.z + vA.z * maskn;
            float add3 = vC.w + vA.w * maskn;
            #pragma unroll
            for (int kk = 0; kk < 8; kk++) {
                int k = ty * 8 + kk;
                float wk = sWk[g][k];
                float4 tv = ((const float4*)(g_T + sSk[g][k] * CDIM))[tx];
                float2 lo = unpack2(acc[kk][0]);
                float2 hi = unpack2(acc[kk][1]);
                float m0 = lo.x + add0 + tv.x * wk;
                float m1 = lo.y + add1 + tv.y * wk;
                float m2 = hi.x + add2 + tv.z * wk;
                float m3 = hi.y + add3 + tv.w * wk;
                float pr = lrelu(m0) * v2.x + lrelu(m1) * v2.y +
                           lrelu(m2) * v2.z + lrelu(m3) * v2.w;
                #pragma unroll
                for (int off = 16; off; off >>= 1)
                    pr += __shfl_xor_sync(0xffffffffu, pr, off);
                if (tx == 0) sLogit[g][k] = pr;
            }
        }
        __syncthreads();

        // softmax over K=32 (warp 0 of each group), fold in w_k for the output sum
        if (ty == 0) {
            float l = sLogit[g][tx];
            float mx = l;
            #pragma unroll
            for (int off = 16; off; off >>= 1)
                mx = fmaxf(mx, __shfl_xor_sync(0xffffffffu, mx, off));
            float e = expf(l - mx);
            float s = e;
            #pragma unroll
            for (int off = 16; off; off >>= 1)
                s += __shfl_xor_sync(0xffffffffu, s, off);
            sAW[g][tx] = (e / s) * sWk[g][tx];
        }
        __syncthreads();

        // out[c] = A[c]*mask + bl2 + bo2 + sum_k (alpha_k*w_k) T[s_k][c]
        {
            float o = g_A[t] * maskn + bl2[t] + bo2[t];
            #pragma unroll
            for (int k = 0; k < KNBR; k++)
                o = fmaf(sAW[g][k], g_T[sSk[g][k] * CDIM + t], o);
            sOut[g][t] = o;
        }
        __syncthreads();

        // logits (V=21) + log_softmax
        if (t < VDIM) {
            float L = b_out[t];
            #pragma unroll 8
            for (int c = 0; c < CDIM; c++)
                L = fmaf(sOut[g][c], W_out[c * VDIM + t], L);
            sLg[g][t] = L;
        }
        __syncthreads();
        if (t == 0) {
            float mx = sLg[g][0];
            for (int v = 1; v < VDIM; v++) mx = fmaxf(mx, sLg[g][v]);
            float s = 0.f;
            for (int v = 0; v < VDIM; v++) s += expf(sLg[g][v] - mx);
            sRed[g][0] = mx;
            sRed[g][1] = logf(s);
        }
        __syncthreads();
        if (t < VDIM)
            out[n * VDIM + t] = sLg[g][t] - sRed[g][0] - sRed[g][1];
    }
}

extern "C" void kernel_launch(void* const* d_in, const int* in_sizes, int n_in,
                              void* d_out, int out_size) {
    const float* E       = (const float*)d_in[0];
    const int*   E_idx   = (const int*)  d_in[1];
    const int*   S       = (const int*)  d_in[2];
    const float* mask    = (const float*)d_in[3];
    const float* chain_M = (const float*)d_in[4];
    const float* z       = (const float*)d_in[5];
    const float* bl1     = (const float*)d_in[7];
    const float* bo1     = (const float*)d_in[13];
    const float* Wl2     = (const float*)d_in[14];
    const float* bl2     = (const float*)d_in[15];
    const float* Wr2     = (const float*)d_in[16];
    const float* br2     = (const float*)d_in[17];
    const float* We2     = (const float*)d_in[18];
    const float* be2     = (const float*)d_in[19];
    const float* a2      = (const float*)d_in[20];
    const float* bo2     = (const float*)d_in[21];
    const float* Ws      = (const float*)d_in[22];
    const float* W_out   = (const float*)d_in[23];
    const float* b_out   = (const float*)d_in[24];
    float* out = (float*)d_out;

    cudaFuncSetAttribute(main_kernel, cudaFuncAttributeMaxDynamicSharedMemorySize, SMEM_BYTES);

    setup_kernel<<<VDIM + 1, 128>>>(bl1, bo1, Wl2, bl2, Wr2, br2, be2, Ws);
    main_kernel<<<304, 256, SMEM_BYTES>>>(E, E_idx, S, mask, chain_M, z,
                                          We2, a2, bl2, bo2, W_out, b_out, out);
}

// round 7
// speedup vs baseline: 1.6166x; 1.0013x over previous
#include <cuda_runtime.h>

#define N_NODES 4096
#define KNBR 32
#define CDIM 128
#define VDIM 21
// We2 (64KB) + two E tiles (2 x 16KB) = 96KB dynamic smem per block
#define SMEM_BYTES ((CDIM*CDIM + 2*KNBR*CDIM) * 4)

__device__ float g_A[CDIM];        // nodevec @ Wl2_top
__device__ float g_const[CDIM];    // xr + br2 + bl2 + be2  (constant part of m)
__device__ float g_T[VDIM * CDIM]; // W_s @ Wl2_bot

__device__ __forceinline__ float lrelu(float x) { return x > 0.f ? x : 0.2f * x; }

__device__ __forceinline__ unsigned long long pack2(float lo, float hi) {
    unsigned long long r;
    asm("mov.b64 %0, {%1, %2};" : "=l"(r) : "f"(lo), "f"(hi));
    return r;
}
__device__ __forceinline__ void ffma2(unsigned long long& d,
                                      unsigned long long a, unsigned long long b) {
    asm("fma.rn.f32x2 %0, %1, %2, %0;" : "+l"(d) : "l"(a), "l"(b));
}
__device__ __forceinline__ float2 unpack2(unsigned long long v) {
    float2 r;
    asm("mov.b64 {%0, %1}, %2;" : "=f"(r.x), "=f"(r.y) : "l"(v));
    return r;
}

// 22 blocks x 128 threads: block 0 -> g_A/g_const, blocks 1..21 -> g_T rows.
__global__ void setup_kernel(const float* __restrict__ bl1, const float* __restrict__ bo1,
                             const float* __restrict__ Wl2, const float* __restrict__ bl2,
                             const float* __restrict__ Wr2, const float* __restrict__ br2,
                             const float* __restrict__ be2, const float* __restrict__ Ws) {
    int c = threadIdx.x;
    int b = blockIdx.x;
    if (b == 0) {
        __shared__ float nv[CDIM];
        nv[c] = bl1[c] + bo1[c];
        __syncthreads();
        float a = 0.f, x = 0.f;
        #pragma unroll 8
        for (int j = 0; j < CDIM; j++) {
            a = fmaf(nv[j], Wl2[j * CDIM + c], a);
            x = fmaf(nv[j], Wr2[j * CDIM + c], x);
        }
        g_A[c] = a;
        g_const[c] = x + br2[c] + bl2[c] + be2[c];
    } else {
        int v = b - 1;
        float t = 0.f;
        #pragma unroll 8
        for (int h = 0; h < CDIM; h++)
            t = fmaf(Ws[v * CDIM + h], Wl2[(CDIM + h) * CDIM + c], t);
        g_T[v * CDIM + c] = t;
    }
}

__global__ void __launch_bounds__(256, 2)
main_kernel(const float* __restrict__ E, const int* __restrict__ E_idx,
            const int* __restrict__ S, const float* __restrict__ mask,
            const float* __restrict__ chain_M, const float* __restrict__ z,
            const float* __restrict__ We2, const float* __restrict__ a2,
            const float* __restrict__ bl2, const float* __restrict__ bo2,
            const float* __restrict__ W_out, const float* __restrict__ b_out,
            float* __restrict__ out) {
    extern __shared__ float smem[];
    float* sW = smem;                 // 128x128 We2
    float* sE = smem + CDIM * CDIM;   // [2][32x128] E tiles
    __shared__ float sLogit[2][KNBR];
    __shared__ float sAW[2][KNBR];
    __shared__ float sWk[2][KNBR];
    __shared__ int   sSk[2][KNBR];
    __shared__ float sOut[2][CDIM];
    __shared__ float sLg[2][VDIM];
    __shared__ float sRed[2][2];

    const int tid = threadIdx.x;
    const int g  = tid >> 7;          // node group 0/1 within the block
    const int t  = tid & 127;         // thread id within group
    const int tx = tid & 31;
    const int ty = t >> 5;            // warp-in-group 0..3

    // Load We2 once per (persistent) block, all 256 threads.
    {
        float4* d = (float4*)sW;
        const float4* s = (const float4*)We2;
        #pragma unroll
        for (int i = 0; i < 16; i++) d[i * 256 + tid] = s[i * 256 + tid];
    }

    float* sEg = sE + g * (KNBR * CDIM);

    for (int p = blockIdx.x; p < N_NODES / 2; p += gridDim.x) {
        const int n = p * 2 + g;
        __syncthreads();  // protect smem reuse across iterations

        // Load this group's E tile (16KB, 128 threads).
        {
            float4* d = (float4*)sEg;
            const float4* s = (const float4*)(E + (size_t)n * KNBR * CDIM);
            #pragma unroll
            for (int i = 0; i < 8; i++) d[i * 128 + t] = s[i * 128 + t];
        }
        const float maskn = mask[n];
        if (t < KNBR) {
            int e = E_idx[n * KNBR + t];
            // stable argsort rank comparison == lexicographic (key, index) comparison
            float kn = __fmul_rn(__fadd_rn(__fmul_rn(chain_M[n], mask[n]), 1e-4f), fabsf(z[n]));
            float ke = __fmul_rn(__fadd_rn(__fmul_rn(chain_M[e], mask[e]), 1e-4f), fabsf(z[e]));
            float attend = (kn > ke || (kn == ke && n > e)) ? 1.f : 0.f;
            sWk[g][t] = attend * maskn;
            sSk[g][t] = S[e];
        }
        __syncthreads();

        // GEMM: M[k][c] = sum_j E[k][j] * We2[j][c]
        // thread owns k = ty*8..+7, c = 4*tx..+3, accumulated as f32x2 pairs.
        unsigned long long acc[8][2];
        #pragma unroll
        for (int kk = 0; kk < 8; kk++) { acc[kk][0] = 0ull; acc[kk][1] = 0ull; }

        const float4* sW4 = (const float4*)sW;
        const float4* sE4 = (const float4*)(sEg + (ty * 8) * CDIM);
        #pragma unroll 2
        for (int j4 = 0; j4 < 32; j4++) {
            unsigned long long wp[4][2];
            #pragma unroll
            for (int js = 0; js < 4; js++) {
                float4 tw = sW4[(4 * j4 + js) * 32 + tx];
                wp[js][0] = pack2(tw.x, tw.y);
                wp[js][1] = pack2(tw.z, tw.w);
            }
            #pragma unroll
            for (int kk = 0; kk < 8; kk++) {
                float4 e4 = sE4[kk * 32 + j4];
                unsigned long long ep;
                ep = pack2(e4.x, e4.x);
                ffma2(acc[kk][0], ep, wp[0][0]); ffma2(acc[kk][1], ep, wp[0][1]);
                ep = pack2(e4.y, e4.y);
                ffma2(acc[kk][0], ep, wp[1][0]); ffma2(acc[kk][1], ep, wp[1][1]);
                ep = pack2(e4.z, e4.z);
                ffma2(acc[kk][0], ep, wp[2][0]); ffma2(acc[kk][1], ep, wp[2][1]);
                ep = pack2(e4.w, e4.w);
                ffma2(acc[kk][0], ep, wp[3][0]); ffma2(acc[kk][1], ep, wp[3][1]);
            }
        }

        // attention logits: logit[k] = sum_c lrelu(M[k][c] + add[c] + T[s_k][c]*w_k) * a2[c]
        {
            float4 vA = ((const float4*)g_A)[tx];
            float4 vC = ((const float4*)g_const)[tx];
            float4 v2 = ((const float4*)a2)[tx];
            float add0 = vC.x + vA.x * maskn;
            float add1 = vC.y + vA.y * maskn;
            float add2 = vC.z + vA.z * maskn;
            float add3 = vC.w + vA.w * maskn;
            #pragma unroll
            for (int kk = 0; kk < 8; kk++) {
                int k = ty * 8 + kk;
                float wk = sWk[g][k];
                float4 tv = ((const float4*)(g_T + sSk[g][k] * CDIM))[tx];
                float2 lo = unpack2(acc[kk][0]);
                float2 hi = unpack2(acc[kk][1]);
                float m0 = lo.x + add0 + tv.x * wk;
                float m1 = lo.y + add1 + tv.y * wk;
                float m2 = hi.x + add2 + tv.z * wk;
                float m3 = hi.y + add3 + tv.w * wk;
                float pr = lrelu(m0) * v2.x + lrelu(m1) * v2.y +
                           lrelu(m2) * v2.z + lrelu(m3) * v2.w;
                #pragma unroll
                for (int off = 16; off; off >>= 1)
                    pr += __shfl_xor_sync(0xffffffffu, pr, off);
                if (tx == 0) sLogit[g][k] = pr;
            }
        }
        __syncthreads();

        // softmax over K=32 (warp 0 of each group), fold in w_k for the output sum
        if (ty == 0) {
            float l = sLogit[g][tx];
            float mx = l;
            #pragma unroll
            for (int off = 16; off; off >>= 1)
                mx = fmaxf(mx, __shfl_xor_sync(0xffffffffu, mx, off));
            float e = expf(l - mx);
            float s = e;
            #pragma unroll
            for (int off = 16; off; off >>= 1)
                s += __shfl_xor_sync(0xffffffffu, s, off);
            sAW[g][tx] = (e / s) * sWk[g][tx];
        }
        __syncthreads();

        // out[c] = A[c]*mask + bl2 + bo2 + sum_k (alpha_k*w_k) T[s_k][c]
        {
            float o = g_A[t] * maskn + bl2[t] + bo2[t];
            #pragma unroll
            for (int k = 0; k < KNBR; k++)
                o = fmaf(sAW[g][k], g_T[sSk[g][k] * CDIM + t], o);
            sOut[g][t] = o;
        }
        __syncthreads();

        // logits (V=21) + log_softmax
        if (t < VDIM) {
            float L = b_out[t];
            #pragma unroll 8
            for (int c = 0; c < CDIM; c++)
                L = fmaf(sOut[g][c], W_out[c * VDIM + t], L);
            sLg[g][t] = L;
        }
        __syncthreads();
        if (t == 0) {
            float mx = sLg[g][0];
            for (int v = 1; v < VDIM; v++) mx = fmaxf(mx, sLg[g][v]);
            float s = 0.f;
            for (int v = 0; v < VDIM; v++) s += expf(sLg[g][v] - mx);
            sRed[g][0] = mx;
            sRed[g][1] = logf(s);
        }
        __syncthreads();
        if (t < VDIM)
            out[n * VDIM + t] = sLg[g][t] - sRed[g][0] - sRed[g][1];
    }
}

extern "C" void kernel_launch(void* const* d_in, const int* in_sizes, int n_in,
                              void* d_out, int out_size) {
    const float* E       = (const float*)d_in[0];
    const int*   E_idx   = (const int*)  d_in[1];
    const int*   S       = (const int*)  d_in[2];
    const float* mask    = (const float*)d_in[3];
    const float* chain_M = (const float*)d_in[4];
    const float* z       = (const float*)d_in[5];
    const float* bl1     = (const float*)d_in[7];
    const float* bo1     = (const float*)d_in[13];
    const float* Wl2     = (const float*)d_in[14];
    const float* bl2     = (const float*)d_in[15];
    const float* Wr2     = (const float*)d_in[16];
    const float* br2     = (const float*)d_in[17];
    const float* We2     = (const float*)d_in[18];
    const float* be2     = (const float*)d_in[19];
    const float* a2      = (const float*)d_in[20];
    const float* bo2     = (const float*)d_in[21];
    const float* Ws      = (const float*)d_in[22];
    const float* W_out   = (const float*)d_in[23];
    const float* b_out   = (const float*)d_in[24];
    float* out = (float*)d_out;

    cudaFuncSetAttribute(main_kernel, cudaFuncAttributeMaxDynamicSharedMemorySize, SMEM_BYTES);

    setup_kernel<<<VDIM + 1, 128>>>(bl1, bo1, Wl2, bl2, Wr2, br2, be2, Ws);
    main_kernel<<<304, 256, SMEM_BYTES>>>(E, E_idx, S, mask, chain_M, z,
                                          We2, a2, bl2, bo2, W_out, b_out, out);
}

// round 9
// speedup vs baseline: 4.2312x; 2.6173x over previous
#include <cuda_runtime.h>
#include <cuda_bf16.h>
#include <stdint.h>

#define N_NODES 4096
#define KNBR 32
#define CDIM 128
#define VDIM 21
#define NUM_TILES (N_NODES / 4)     // 4 nodes per tile, M = 128 rows
#define APAD 136                    // padded bf16 row stride (68 words) -> conflict-free frags
#define AWORDS (128 * 68)           // words per 128x136 bf16 tile
#define DYN_SMEM (2 * AWORDS * 4)   // A tile + B tile (We2^T)

__device__ float g_A[CDIM];
__device__ float g_const[CDIM];
__device__ float g_T[VDIM * CDIM];

__device__ __forceinline__ float lrelu(float x) { return x > 0.f ? x : 0.2f * x; }

__device__ __forceinline__ void mma16816(float* c, uint32_t a0, uint32_t a1,
                                         uint32_t a2, uint32_t a3,
                                         uint32_t b0, uint32_t b1) {
    asm volatile("mma.sync.aligned.m16n8k16.row.col.f32.bf16.bf16.f32 "
                 "{%0,%1,%2,%3}, {%4,%5,%6,%7}, {%8,%9}, {%0,%1,%2,%3};"
                 : "+f"(c[0]), "+f"(c[1]), "+f"(c[2]), "+f"(c[3])
                 : "r"(a0), "r"(a1), "r"(a2), "r"(a3), "r"(b0), "r"(b1));
}

// 22 blocks x 128 threads: block 0 -> g_A/g_const, blocks 1..21 -> g_T rows.
__global__ void setup_kernel(const float* __restrict__ bl1, const float* __restrict__ bo1,
                             const float* __restrict__ Wl2, const float* __restrict__ bl2,
                             const float* __restrict__ Wr2, const float* __restrict__ br2,
                             const float* __restrict__ be2, const float* __restrict__ Ws) {
    int c = threadIdx.x;
    int b = blockIdx.x;
    if (b == 0) {
        __shared__ float nv[CDIM];
        nv[c] = bl1[c] + bo1[c];
        __syncthreads();
        float a = 0.f, x = 0.f;
        #pragma unroll 8
        for (int j = 0; j < CDIM; j++) {
            a = fmaf(nv[j], Wl2[j * CDIM + c], a);
            x = fmaf(nv[j], Wr2[j * CDIM + c], x);
        }
        g_A[c] = a;
        g_const[c] = x + br2[c] + bl2[c] + be2[c];
    } else {
        int v = b - 1;
        float t = 0.f;
        #pragma unroll 8
        for (int h = 0; h < CDIM; h++)
            t = fmaf(Ws[v * CDIM + h], Wl2[(CDIM + h) * CDIM + c], t);
        g_T[v * CDIM + c] = t;
    }
}

__global__ void __launch_bounds__(256, 2)
main_kernel(const float* __restrict__ E, const int* __restrict__ E_idx,
            const int* __restrict__ S, const float* __restrict__ mask,
            const float* __restrict__ chain_M, const float* __restrict__ z,
            const float* __restrict__ We2, const float* __restrict__ a2,
            const float* __restrict__ bl2, const float* __restrict__ bo2,
            const float* __restrict__ W_out, const float* __restrict__ b_out,
            float* __restrict__ out) {
    extern __shared__ uint32_t dsm32[];
    uint32_t* Asm = dsm32;            // E tile, bf16 [128][136]
    uint32_t* Bsm = dsm32 + AWORDS;   // We2^T, bf16 [128][136]: B[c][j] = We2[j][c]

    __shared__ float sT[VDIM * 129];  // padded -> low-conflict row reads
    __shared__ float sAdd[4][CDIM];
    __shared__ float sa2[CDIM];
    __shared__ float sB2[CDIM];       // bl2 + bo2
    __shared__ float sWk[128];
    __shared__ int   sSk[128];
    __shared__ float sLogit[128];
    __shared__ float sAW[4][KNBR];
    __shared__ float sOut[4][CDIM];

    const int tid  = threadIdx.x;
    const int w    = tid >> 5;        // 0..7
    const int lane = tid & 31;
    const int gq   = lane >> 2;       // quad group 0..7
    const int tq   = lane & 3;        // thread-in-quad 0..3

    // one-time: We2^T -> B tile (bf16); constants into smem
    for (int i = tid; i < CDIM * CDIM; i += 256) {
        int c = i & 127, j = i >> 7;  // coalesced over c
        ((__nv_bfloat16*)Bsm)[c * APAD + j] = __float2bfloat16(We2[j * CDIM + c]);
    }
    for (int i = tid; i < VDIM * CDIM; i += 256)
        sT[(i >> 7) * 129 + (i & 127)] = g_T[i];
    if (tid < CDIM) {
        sa2[tid] = a2[tid];
        sB2[tid] = bl2[tid] + bo2[tid];
    }
    __syncthreads();

    for (int tile = blockIdx.x; tile < NUM_TILES; tile += gridDim.x) {
        // per-row metadata: row r = node_local*32 + k
        if (tid < 128) {
            int n = tile * 4 + (tid >> 5);
            int k = tid & 31;
            int e = E_idx[n * KNBR + k];
            float kn = __fmul_rn(__fadd_rn(__fmul_rn(chain_M[n], mask[n]), 1e-4f), fabsf(z[n]));
            float ke = __fmul_rn(__fadd_rn(__fmul_rn(chain_M[e], mask[e]), 1e-4f), fabsf(z[e]));
            float attend = (kn > ke || (kn == ke && n > e)) ? 1.f : 0.f;
            sWk[tid] = attend * mask[n];
            sSk[tid] = S[e];
        }
        #pragma unroll
        for (int q = 0; q < 2; q++) {
            int idx = tid + q * 256;  // 512 entries: sAdd[4][128]
            int nd = idx >> 7, c = idx & 127;
            sAdd[nd][c] = fmaf(g_A[c], mask[tile * 4 + nd], g_const[c]);
        }

        // E tile (128 rows x 128 fp32) -> A smem bf16 padded row-major
        {
            const float4* E4 = (const float4*)E + (size_t)tile * 4096;
            #pragma unroll
            for (int it = 0; it < 16; it++) {
                int f = it * 256 + tid;          // one float4 = 4 j of one row
                float4 v = E4[f];
                int r = f >> 5, j0 = (f & 31) * 4;
                __nv_bfloat162 p0 = __floats2bfloat162_rn(v.x, v.y);
                __nv_bfloat162 p1 = __floats2bfloat162_rn(v.z, v.w);
                *(uint2*)(Asm + r * 68 + (j0 >> 1)) =
                    make_uint2(*(uint32_t*)&p0, *(uint32_t*)&p1);
            }
        }
        __syncthreads();

        // GEMM via mma.sync: warp w owns rows 16w..16w+15, all 128 cols.
        // D[r][c] = sum_j A[r][j] * B[c][j]   (B col-major k x n = We2^T rows)
        float acc[16][4];
        #pragma unroll
        for (int nt = 0; nt < 16; nt++)
            #pragma unroll
            for (int i = 0; i < 4; i++) acc[nt][i] = 0.f;

        const uint32_t* Aw = Asm + (16 * w + gq) * 68;  // row r0
        #pragma unroll
        for (int s = 0; s < 8; s++) {
            const int jo = s * 8 + tq;
            uint32_t a0 = Aw[jo];
            uint32_t a1 = Aw[8 * 68 + jo];
            uint32_t a2r = Aw[jo + 4];
            uint32_t a3 = Aw[8 * 68 + jo + 4];
            #pragma unroll
            for (int nt = 0; nt < 16; nt++) {
                const uint32_t* Bn = Bsm + (nt * 8 + gq) * 68;
                uint32_t b0 = Bn[jo];
                uint32_t b1 = Bn[jo + 4];
                mma16816(acc[nt], a0, a1, a2r, a3, b0, b1);
            }
        }

        // epilogue: thread holds rows r0=16w+gq, r1=r0+8; cols nt*8 + tq*2 + {0,1}
        {
            const int r0 = 16 * w + gq, r1 = r0 + 8;
            const int nd = w >> 1;
            const float wk0 = sWk[r0], wk1 = sWk[r1];
            const float* T0 = &sT[sSk[r0] * 129];
            const float* T1 = &sT[sSk[r1] * 129];
            float p0 = 0.f, p1 = 0.f;
            #pragma unroll
            for (int nt = 0; nt < 16; nt++) {
                #pragma unroll
                for (int i = 0; i < 2; i++) {
                    const int c = nt * 8 + tq * 2 + i;
                    const float ad = sAdd[nd][c];
                    const float av = sa2[c];
                    p0 = fmaf(lrelu(acc[nt][i]     + ad + T0[c] * wk0), av, p0);
                    p1 = fmaf(lrelu(acc[nt][2 + i] + ad + T1[c] * wk1), av, p1);
                }
            }
            p0 += __shfl_xor_sync(0xffffffffu, p0, 1);
            p0 += __shfl_xor_sync(0xffffffffu, p0, 2);
            p1 += __shfl_xor_sync(0xffffffffu, p1, 1);
            p1 += __shfl_xor_sync(0xffffffffu, p1, 2);
            if (tq == 0) { sLogit[r0] = p0; sLogit[r1] = p1; }
        }
        __syncthreads();

        // softmax over K=32 per node (warps 0-3, node = w)
        if (w < 4) {
            float logit = sLogit[w * 32 + lane];
            float mx = logit;
            #pragma unroll
            for (int off = 16; off; off >>= 1)
                mx = fmaxf(mx, __shfl_xor_sync(0xffffffffu, mx, off));
            float e = expf(logit - mx);
            float s = e;
            #pragma unroll
            for (int off = 16; off; off >>= 1)
                s += __shfl_xor_sync(0xffffffffu, s, off);
            sAW[w][lane] = (e / s) * sWk[w * 32 + lane];
        }
        __syncthreads();

        // out[c] = A[c]*maskn + bl2+bo2 + sum_k aw_k * T[sk][c]; 64 threads/node, 2 cols each
        {
            int nd2 = tid >> 6, c0 = (tid & 63) * 2;
            float maskn = mask[tile * 4 + nd2];
            float o0 = fmaf(g_A[c0],     maskn, sB2[c0]);
            float o1 = fmaf(g_A[c0 + 1], maskn, sB2[c0 + 1]);
            #pragma unroll
            for (int k = 0; k < KNBR; k++) {
                float aw = sAW[nd2][k];
                const float* tr = &sT[sSk[nd2 * 32 + k] * 129];
                o0 = fmaf(aw, tr[c0], o0);
                o1 = fmaf(aw, tr[c0 + 1], o1);
            }
            sOut[nd2][c0] = o0;
            sOut[nd2][c0 + 1] = o1;
        }
        __syncthreads();

        // logits (V=21) + log_softmax: warp w<4 handles node w
        if (w < 4) {
            float L = -1e30f;
            if (lane < VDIM) {
                L = b_out[lane];
                #pragma unroll 8
                for (int c = 0; c < CDIM; c++)
                    L = fmaf(sOut[w][c], W_out[c * VDIM + lane], L);
            }
            float mx = L;
            #pragma unroll
            for (int off = 16; off; off >>= 1)
                mx = fmaxf(mx, __shfl_xor_sync(0xffffffffu, mx, off));
            float e = (lane < VDIM) ? expf(L - mx) : 0.f;
            float s = e;
            #pragma unroll
            for (int off = 16; off; off >>= 1)
                s += __shfl_xor_sync(0xffffffffu, s, off);
            if (lane < VDIM)
                out[(tile * 4 + w) * VDIM + lane] = L - mx - logf(s);
        }
        __syncthreads();  // guard sWk/sAdd/A-tile overwrite next iteration
    }
}

extern "C" void kernel_launch(void* const* d_in, const int* in_sizes, int n_in,
                              void* d_out, int out_size) {
    const float* E       = (const float*)d_in[0];
    const int*   E_idx   = (const int*)  d_in[1];
    const int*   S       = (const int*)  d_in[2];
    const float* mask    = (const float*)d_in[3];
    const float* chain_M = (const float*)d_in[4];
    const float* z       = (const float*)d_in[5];
    const float* bl1     = (const float*)d_in[7];
    const float* bo1     = (const float*)d_in[13];
    const float* Wl2     = (const float*)d_in[14];
    const float* bl2     = (const float*)d_in[15];
    const float* Wr2     = (const float*)d_in[16];
    const float* br2     = (const float*)d_in[17];
    const float* We2     = (const float*)d_in[18];
    const float* be2     = (const float*)d_in[19];
    const float* a2      = (const float*)d_in[20];
    const float* bo2     = (const float*)d_in[21];
    const float* Ws      = (const float*)d_in[22];
    const float* W_out   = (const float*)d_in[23];
    const float* b_out   = (const float*)d_in[24];
    float* out = (float*)d_out;

    cudaFuncSetAttribute(main_kernel, cudaFuncAttributeMaxDynamicSharedMemorySize, DYN_SMEM);

    setup_kernel<<<VDIM + 1, 128>>>(bl1, bo1, Wl2, bl2, Wr2, br2, be2, Ws);
    main_kernel<<<304, 256, DYN_SMEM>>>(E, E_idx, S, mask, chain_M, z,
                                        We2, a2, bl2, bo2, W_out, b_out, out);
}